// round 1
// baseline (speedup 1.0000x reference)
#include <cuda_runtime.h>
#include <math.h>

#define BB      8
#define TT      512
#define DIMIN   768
#define WIDTH   8192
#define NHEADS  8
#define NEMBDS  128
#define DH_QK   16
#define DH_V    1024
#define MM      (BB * TT)          /* 4096 */
#define LAM     (1.0f / 3072.0f)   /* 1/(4*DIMIN) */
#define EPSV    1e-6f

// ---------------- scratch (static device globals; no allocation) ------------
__device__ float g_x    [MM * DIMIN];
__device__ float g_x2   [MM * DIMIN];
__device__ float g_zin  [MM * WIDTH];
__device__ float g_zctx [MM * WIDTH];
__device__ float g_q    [MM * NEMBDS];
__device__ float g_k    [MM * NEMBDS];
__device__ float g_v    [MM * WIDTH];
__device__ float g_probs[(long)BB * NHEADS * TT * TT];
__device__ float g_attno[MM * WIDTH];
__device__ float g_zpred[MM * WIDTH];
__device__ float g_Dz   [MM * DIMIN];
__device__ float g_proj [MM];
__device__ float g_znov [MM * WIDTH];
__device__ float g_zsum [MM * WIDTH];

// ---------------- small elementwise kernels ---------------------------------
__global__ void prep_kernel(const float* __restrict__ xin,
                            const float* __restrict__ bvec) {
    int idx = blockIdx.x * blockDim.x + threadIdx.x;       // over MM*DIMIN/4
    if (idx >= MM * (DIMIN / 4)) return;
    int c4 = idx % (DIMIN / 4);
    float4 xv = ((const float4*)xin)[idx];
    float4 bv = ((const float4*)bvec)[c4];
    float4 r = make_float4(xv.x - bv.x, xv.y - bv.y, xv.z - bv.z, xv.w - bv.w);
    ((float4*)g_x)[idx] = r;
}

__global__ void shift_kernel() {
    long idx = (long)blockIdx.x * blockDim.x + threadIdx.x;  // MM*WIDTH/4
    if (idx >= (long)MM * (WIDTH / 4)) return;
    int row = (int)(idx / (WIDTH / 4));
    int t = row % TT;
    float4 v = (t == 0) ? make_float4(0.f, 0.f, 0.f, 0.f)
                        : ((const float4*)g_zin)[idx - (WIDTH / 4)];
    ((float4*)g_zctx)[idx] = v;
}

// ---------------- generic 128x128x8 SGEMM (NT / NN) --------------------------
// C[m,n] = act( alpha * sum_k A[m,k] * B(n,k) + bias[n] )
// TRANSB=true : B is (N x K) row-major (B(n,k)=B[n*ldb+k])
// TRANSB=false: B is (K x N) row-major (B(n,k)=B[k*ldb+n])
// All M, N, K are multiples of 128/128/8 for every launch in this file.
template<bool TRANSB, bool RELU, bool BIAS>
__global__ void __launch_bounds__(256, 2) gemm_kernel(
    const float* __restrict__ A, int lda,
    const float* __restrict__ Bp, int ldb,
    float* __restrict__ C, int ldc,
    int K, float alpha, const float* __restrict__ bias,
    long sA, int zdiv, long sBo, long sBi, long sCo, long sCi)
{
    int z = blockIdx.z;
    A  += (long)z * sA;
    Bp += (long)(z / zdiv) * sBo + (long)(z % zdiv) * sBi;
    C  += (long)(z / zdiv) * sCo + (long)(z % zdiv) * sCi;

    const int m0 = blockIdx.y * 128;
    const int n0 = blockIdx.x * 128;

    __shared__ float As[8][128];
    __shared__ float Bs[8][128];

    const int tid = threadIdx.x;
    const int tx = tid & 15;       // 0..15, 8 cols each
    const int ty = tid >> 4;       // 0..15, 8 rows each

    float acc[8][8];
#pragma unroll
    for (int i = 0; i < 8; i++)
#pragma unroll
        for (int j = 0; j < 8; j++) acc[i][j] = 0.f;

    const int ar = tid >> 1;         // 0..127
    const int aK = (tid & 1) * 4;    // 0 or 4

    const float* Aload = A + (long)(m0 + ar) * lda + aK;
    const float* Bload;
    if (TRANSB) Bload = Bp + (long)(n0 + ar) * ldb + aK;
    else        Bload = Bp + (long)(tid >> 5) * ldb + n0 + (tid & 31) * 4;

    for (int kt = 0; kt < K; kt += 8) {
        float4 av = *(const float4*)Aload;
        As[aK + 0][ar] = av.x;
        As[aK + 1][ar] = av.y;
        As[aK + 2][ar] = av.z;
        As[aK + 3][ar] = av.w;
        if (TRANSB) {
            float4 bv = *(const float4*)Bload;
            Bs[aK + 0][ar] = bv.x;
            Bs[aK + 1][ar] = bv.y;
            Bs[aK + 2][ar] = bv.z;
            Bs[aK + 3][ar] = bv.w;
        } else {
            float4 bv = *(const float4*)Bload;
            *(float4*)&Bs[tid >> 5][(tid & 31) * 4] = bv;
        }
        __syncthreads();
#pragma unroll
        for (int k = 0; k < 8; k++) {
            float a[8], b[8];
            *(float4*)&a[0] = *(const float4*)&As[k][ty * 8];
            *(float4*)&a[4] = *(const float4*)&As[k][ty * 8 + 4];
            *(float4*)&b[0] = *(const float4*)&Bs[k][tx * 8];
            *(float4*)&b[4] = *(const float4*)&Bs[k][tx * 8 + 4];
#pragma unroll
            for (int i = 0; i < 8; i++)
#pragma unroll
                for (int j = 0; j < 8; j++) acc[i][j] += a[i] * b[j];
        }
        __syncthreads();
        Aload += 8;
        Bload += TRANSB ? 8 : (long)8 * ldb;
    }

    float bcol[8];
#pragma unroll
    for (int j = 0; j < 8; j++)
        bcol[j] = BIAS ? bias[n0 + tx * 8 + j] : 0.f;

#pragma unroll
    for (int i = 0; i < 8; i++) {
        int m = m0 + ty * 8 + i;
        float out[8];
#pragma unroll
        for (int j = 0; j < 8; j++) {
            float v = alpha * acc[i][j];
            if (BIAS) v += bcol[j];
            if (RELU) v = fmaxf(v, 0.f);
            out[j] = v;
        }
        float* cp = C + (long)m * ldc + n0 + tx * 8;
        *(float4*)(cp)     = *(float4*)&out[0];
        *(float4*)(cp + 4) = *(float4*)&out[4];
    }
}

// ---------------- attention: scores + causal softmax -------------------------
// one thread per query row; k-tile for the head cached in smem
__global__ void attn_scores_kernel() {
    int bh = blockIdx.x;
    int b = bh / NHEADS, h = bh % NHEADS;
    int t = blockIdx.y * 128 + threadIdx.x;   // query index 0..511

    __shared__ float kk[TT][DH_QK];           // 32 KB
    const float* kbase = g_k + (long)b * TT * NEMBDS + h * DH_QK;
    for (int i = threadIdx.x; i < TT * (DH_QK / 4); i += 128) {
        int row = i >> 2, c4 = i & 3;
        ((float4*)&kk[row][0])[c4] =
            *(const float4*)(kbase + (long)row * NEMBDS + c4 * 4);
    }
    __syncthreads();

    float qv[DH_QK];
    const float* qb = g_q + (long)(b * TT + t) * NEMBDS + h * DH_QK;
#pragma unroll
    for (int d = 0; d < DH_QK; d++) qv[d] = qb[d];

    float* prow = g_probs + ((long)bh * TT + t) * TT;

    float mx = -1e30f;
    for (int tp = 0; tp <= t; tp++) {
        float s = 0.f;
#pragma unroll
        for (int d = 0; d < DH_QK; d++) s += qv[d] * kk[tp][d];
        s *= 0.25f;                 // 1/sqrt(16)
        mx = fmaxf(mx, s);
        prow[tp] = s;
    }
    float sum = 0.f;
    for (int tp = 0; tp <= t; tp++) sum += __expf(prow[tp] - mx);
    float inv = 1.f / sum;
    for (int tp = 0; tp < TT; tp++) {
        float p = (tp <= t) ? __expf(prow[tp] - mx) * inv : 0.f;
        prow[tp] = p;
    }
}

// ---------------- projection + residual update -------------------------------
__global__ void proj_kernel() {
    int m = blockIdx.x;
    int tid = threadIdx.x;   // 256
    const float* dz = g_Dz + (long)m * DIMIN;
    const float* x  = g_x  + (long)m * DIMIN;

    float num = 0.f, den = 0.f;
    for (int j = tid; j < DIMIN; j += 256) {
        float a = dz[j], c = x[j];
        num += a * c;
        den += a * a;
    }
#pragma unroll
    for (int o = 16; o > 0; o >>= 1) {
        num += __shfl_down_sync(0xFFFFFFFFu, num, o);
        den += __shfl_down_sync(0xFFFFFFFFu, den, o);
    }
    __shared__ float sn[8], sd[8];
    __shared__ float s_proj;
    int lane = tid & 31, wid = tid >> 5;
    if (lane == 0) { sn[wid] = num; sd[wid] = den; }
    __syncthreads();
    if (tid == 0) {
        float N = 0.f, Dd = 0.f;
#pragma unroll
        for (int i = 0; i < 8; i++) { N += sn[i]; Dd += sd[i]; }
        float p = N / (Dd + EPSV);
        s_proj = p;
        g_proj[m] = p;
    }
    __syncthreads();
    float p = s_proj;
    for (int j = tid; j < DIMIN; j += 256)
        g_x2[(long)m * DIMIN + j] = x[j] - p * dz[j];
}

// ---------------- top-k mask (radix select) + z_pred scale + sum -------------
__global__ void topk_zsum_kernel(const int* __restrict__ kvalp) {
    int m = blockIdx.x;
    int tid = threadIdx.x;   // 256

    __shared__ unsigned sv[WIDTH];        // 32 KB; relu'd floats: bits monotone
    __shared__ int hist[256];
    __shared__ int s_target;
    __shared__ unsigned s_prefix, s_mask;

    const float* zn = g_znov + (long)m * WIDTH;
    for (int j = tid; j < WIDTH; j += 256)
        sv[j] = __float_as_uint(zn[j]);
    if (tid == 0) { s_target = *kvalp; s_prefix = 0u; s_mask = 0u; }
    __syncthreads();

    for (int byte = 3; byte >= 0; --byte) {
        hist[tid] = 0;
        __syncthreads();
        int shift = byte * 8;
        unsigned pm = s_mask, pf = s_prefix;
        for (int j = tid; j < WIDTH; j += 256) {
            unsigned v = sv[j];
            if ((v & pm) == pf) atomicAdd(&hist[(v >> shift) & 255], 1);
        }
        __syncthreads();
        if (tid == 0) {
            int cum = 0, tgt = s_target, sel = 0;
            for (int bin = 255; bin >= 0; --bin) {
                int c = hist[bin];
                if (cum + c >= tgt) { sel = bin; break; }
                cum += c;
            }
            s_target = tgt - cum;
            s_prefix = pf | ((unsigned)sel << shift);
            s_mask   = pm | (0xFFu << shift);
        }
        __syncthreads();
    }
    unsigned tau = s_prefix;  // value of the k-th largest (bit pattern)
    float p = g_proj[m];
    const float* zp = g_zpred + (long)m * WIDTH;
    float* out = g_zsum + (long)m * WIDTH;
    for (int j = tid; j < WIDTH; j += 256) {
        unsigned v = sv[j];
        float zval = (v >= tau) ? __uint_as_float(v) : 0.f;
        out[j] = zval + p * zp[j];
    }
}

// ---------------- launcher ---------------------------------------------------
extern "C" void kernel_launch(void* const* d_in, const int* in_sizes, int n_in,
                              void* d_out, int out_size)
{
    const float* x_input = (const float*)d_in[0];
    const float* D       = (const float*)d_in[1];
    const float* bvec    = (const float*)d_in[2];
    const float* Wk      = (const float*)d_in[3];
    const float* bk      = (const float*)d_in[4];
    const float* Wq      = (const float*)d_in[5];
    const float* bq      = (const float*)d_in[6];
    const float* Wv      = (const float*)d_in[7];
    const float* bv      = (const float*)d_in[8];
    const float* Wo      = (const float*)d_in[9];
    const float* bo      = (const float*)d_in[10];
    const int*   kval    = (const int*)d_in[11];

    float *px, *px2, *pzin, *pzctx, *pq, *pk, *pv, *pprobs, *pattno,
          *pzpred, *pDz, *pzsum, *pznov;
    cudaGetSymbolAddress((void**)&px,     g_x);
    cudaGetSymbolAddress((void**)&px2,    g_x2);
    cudaGetSymbolAddress((void**)&pzin,   g_zin);
    cudaGetSymbolAddress((void**)&pzctx,  g_zctx);
    cudaGetSymbolAddress((void**)&pq,     g_q);
    cudaGetSymbolAddress((void**)&pk,     g_k);
    cudaGetSymbolAddress((void**)&pv,     g_v);
    cudaGetSymbolAddress((void**)&pprobs, g_probs);
    cudaGetSymbolAddress((void**)&pattno, g_attno);
    cudaGetSymbolAddress((void**)&pzpred, g_zpred);
    cudaGetSymbolAddress((void**)&pDz,    g_Dz);
    cudaGetSymbolAddress((void**)&pznov,  g_znov);
    cudaGetSymbolAddress((void**)&pzsum,  g_zsum);

    // 1) x = x_input - b
    prep_kernel<<<(MM * (DIMIN / 4) + 255) / 256, 256>>>(x_input, bvec);

    // 2) z_in = relu(lam * x @ D^T)           (4096 x 8192, K=768)
    gemm_kernel<true, true, false><<<dim3(WIDTH / 128, MM / 128, 1), 256>>>(
        px, DIMIN, D, DIMIN, pzin, WIDTH, DIMIN, LAM, nullptr, 0, 1, 0, 0, 0, 0);

    // 3) z_ctx = shift(z_in)
    shift_kernel<<<(int)(((long)MM * (WIDTH / 4) + 255) / 256), 256>>>();

    // 4) k = z_ctx @ Wk^T + bk                (4096 x 128, K=8192)
    gemm_kernel<true, false, true><<<dim3(NEMBDS / 128, MM / 128, 1), 256>>>(
        pzctx, WIDTH, Wk, WIDTH, pk, NEMBDS, WIDTH, 1.f, bk, 0, 1, 0, 0, 0, 0);

    // 5) q = z_in @ Wq^T + bq
    gemm_kernel<true, false, true><<<dim3(NEMBDS / 128, MM / 128, 1), 256>>>(
        pzin, WIDTH, Wq, WIDTH, pq, NEMBDS, WIDTH, 1.f, bq, 0, 1, 0, 0, 0, 0);

    // 6) v = z_ctx @ Wv^T + bv                (4096 x 8192, K=8192)
    gemm_kernel<true, false, true><<<dim3(WIDTH / 128, MM / 128, 1), 256>>>(
        pzctx, WIDTH, Wv, WIDTH, pv, WIDTH, WIDTH, 1.f, bv, 0, 1, 0, 0, 0, 0);

    // 7) causal softmax probs
    attn_scores_kernel<<<dim3(BB * NHEADS, TT / 128), 128>>>();

    // 8) o = P @ V per (b,h), written into (B,T, h*1024+d) layout
    gemm_kernel<false, false, false><<<dim3(DH_V / 128, TT / 128, BB * NHEADS), 256>>>(
        pprobs, TT, pv, WIDTH, pattno, WIDTH, TT, 1.f, nullptr,
        (long)TT * TT, NHEADS,
        (long)TT * WIDTH, (long)DH_V,
        (long)TT * WIDTH, (long)DH_V);

    // 9) z_pred_ = relu(o @ Wo^T + bo)        (4096 x 8192, K=8192)
    gemm_kernel<true, true, true><<<dim3(WIDTH / 128, MM / 128, 1), 256>>>(
        pattno, WIDTH, Wo, WIDTH, pzpred, WIDTH, WIDTH, 1.f, bo, 0, 1, 0, 0, 0, 0);

    // 10) Dz = z_pred_ @ D                    (4096 x 768, K=8192)
    gemm_kernel<false, false, false><<<dim3(DIMIN / 128, MM / 128, 1), 256>>>(
        pzpred, WIDTH, D, DIMIN, pDz, DIMIN, WIDTH, 1.f, nullptr, 0, 1, 0, 0, 0, 0);

    // 11) proj + x residual update
    proj_kernel<<<MM, 256>>>();

    // 12) z_novel = relu(lam * x2 @ D^T)
    gemm_kernel<true, true, false><<<dim3(WIDTH / 128, MM / 128, 1), 256>>>(
        px2, DIMIN, D, DIMIN, pznov, WIDTH, DIMIN, LAM, nullptr, 0, 1, 0, 0, 0, 0);

    // 13) top-k mask + proj*z_pred_ sum
    topk_zsum_kernel<<<MM, 256>>>(kval);

    // 14) x_recons = zsum @ D + b  -> d_out
    gemm_kernel<false, false, true><<<dim3(DIMIN / 128, MM / 128, 1), 256>>>(
        pzsum, WIDTH, D, DIMIN, (float*)d_out, DIMIN, WIDTH, 1.f, bvec, 0, 1, 0, 0, 0, 0);
}

// round 3
// speedup vs baseline: 4.5410x; 4.5410x over previous
#include <cuda_runtime.h>
#include <cuda_bf16.h>
#include <math.h>

#define BB      8
#define TT      512
#define DIMIN   768
#define WIDTH   8192
#define NHEADS  8
#define NEMBDS  128
#define DH_QK   16
#define DH_V    1024
#define MM      (BB * TT)          /* 4096 */
#define LAM     (1.0f / 3072.0f)
#define EPSV    1e-6f
#define KT      64                 /* K-tile in elements (128B bf16 rows) */

// ---------------- scratch ----------------------------------------------------
__device__ float g_x    [MM * DIMIN];
__device__ float g_x2   [MM * DIMIN];
__device__ float g_zin  [MM * WIDTH];
__device__ float g_q    [MM * NEMBDS];
__device__ float g_k    [MM * NEMBDS];
__device__ float g_v    [MM * WIDTH];
__device__ float g_probs[(long)BB * NHEADS * TT * TT];
__device__ float g_attno[MM * WIDTH];
__device__ float g_zpred[MM * WIDTH];
__device__ float g_Dz   [MM * DIMIN];
__device__ float g_proj [MM];
__device__ float g_znov [MM * WIDTH];
__device__ float g_zsum [MM * WIDTH];

// ---------------- helpers ----------------------------------------------------
__device__ __forceinline__ unsigned smem_u32(const void* p) {
    unsigned a;
    asm("{ .reg .u64 t; cvta.to.shared.u64 t, %1; cvt.u32.u64 %0, t; }"
        : "=r"(a) : "l"(p));
    return a;
}
__device__ __forceinline__ unsigned swz(unsigned off) {   // SW128 xor swizzle
    return off ^ ((off >> 3) & 0x70);
}

#define LDSM4(r, a)                                                             \
    asm volatile("ldmatrix.sync.aligned.m8n8.x4.shared.b16 {%0,%1,%2,%3},[%4];" \
                 : "=r"((r)[0]), "=r"((r)[1]), "=r"((r)[2]), "=r"((r)[3])       \
                 : "r"(a))
#define LDSM2(r, a)                                                             \
    asm volatile("ldmatrix.sync.aligned.m8n8.x2.shared.b16 {%0,%1},[%2];"       \
                 : "=r"((r)[0]), "=r"((r)[1]) : "r"(a))
#define MMA(d, a, b)                                                            \
    asm volatile("mma.sync.aligned.m16n8k16.row.col.f32.bf16.bf16.f32 "         \
                 "{%0,%1,%2,%3},{%4,%5,%6,%7},{%8,%9},{%0,%1,%2,%3};"           \
                 : "+f"((d)[0]), "+f"((d)[1]), "+f"((d)[2]), "+f"((d)[3])       \
                 : "r"((a)[0]), "r"((a)[1]), "r"((a)[2]), "r"((a)[3]),          \
                   "r"((b)[0]), "r"((b)[1]))

// fp32 -> (hi bf16, lo bf16) split of 4 elems, store 8B each to smem
__device__ __forceinline__ void split_store(float a0, float a1, float a2, float a3,
                                            char* hip, char* lop) {
    __nv_bfloat162 h01 = __floats2bfloat162_rn(a0, a1);
    __nv_bfloat162 h23 = __floats2bfloat162_rn(a2, a3);
    float r0 = a0 - __bfloat162float(h01.x);
    float r1 = a1 - __bfloat162float(h01.y);
    float r2 = a2 - __bfloat162float(h23.x);
    float r3 = a3 - __bfloat162float(h23.y);
    __nv_bfloat162 l01 = __floats2bfloat162_rn(r0, r1);
    __nv_bfloat162 l23 = __floats2bfloat162_rn(r2, r3);
    *(uint2*)hip = make_uint2(*(unsigned*)&h01, *(unsigned*)&h23);
    *(uint2*)lop = make_uint2(*(unsigned*)&l01, *(unsigned*)&l23);
}

// ---------------- split-bf16 mma.sync GEMM -----------------------------------
// C[m,n] = act( alpha * sum_k A[m,k] * B(n,k) + bias[n] )
// TRANSB=1: B (N x K) row-major.  TRANSB=0: B (K x N) row-major.
// SHIFT=1:  A row m reads source row m-1 (zeros when m % TT == 0).
template<bool TRANSB, bool RELU, bool BIAS, bool SHIFT>
__global__ void __launch_bounds__(256, 1) tgemm(
    const float* __restrict__ A, int lda,
    const float* __restrict__ Bp, int ldb,
    float* __restrict__ C, int ldc,
    int K, float alpha, const float* __restrict__ bias,
    long sA, int zdiv, long sBo, long sBi, long sCo, long sCi)
{
    extern __shared__ char sm[];
    const int TB = 128 * KT * 2;         // 16 KB per tile buffer
    char* AH = sm;                       // [2][TB]
    char* AL = sm + 2 * TB;
    char* BH = sm + 4 * TB;
    char* BL = sm + 6 * TB;

    const int z = blockIdx.z;
    A  += (long)z * sA;
    Bp += (long)(z / zdiv) * sBo + (long)(z % zdiv) * sBi;
    C  += (long)(z / zdiv) * sCo + (long)(z % zdiv) * sCi;
    const int m0 = blockIdx.y * 128;
    const int n0 = blockIdx.x * 128;

    const int tid = threadIdx.x, wid = tid >> 5, lane = tid & 31;
    const int mw = (wid & 1) * 64;       // warp tile: 64 x 32
    const int nw = (wid >> 1) * 32;

    const unsigned sb = smem_u32(sm);
    const unsigned uAH = sb, uAL = sb + 2 * TB, uBH = sb + 4 * TB, uBL = sb + 6 * TB;

    float acc[4][4][4];
#pragma unroll
    for (int i = 0; i < 4; i++)
#pragma unroll
        for (int j = 0; j < 4; j++)
#pragma unroll
            for (int l = 0; l < 4; l++) acc[i][j][l] = 0.f;

    float4 ra[8], rb[8];

    // ---- loaders: global -> regs ----
    auto loadA = [&](int kt) {
#pragma unroll
        for (int i = 0; i < 8; i++) {
            int idx = i * 256 + tid;          // 0..2047
            int row = idx >> 4;               // 0..127
            int k0  = (idx & 15) * 4;
            if (SHIFT) {
                int gr = m0 + row;
                ra[i] = ((gr % TT) == 0) ? make_float4(0.f, 0.f, 0.f, 0.f)
                        : *(const float4*)(A + (long)(gr - 1) * lda + kt * KT + k0);
            } else {
                ra[i] = *(const float4*)(A + (long)(m0 + row) * lda + kt * KT + k0);
            }
        }
    };
    auto loadB = [&](int kt) {
        if (TRANSB) {
#pragma unroll
            for (int i = 0; i < 8; i++) {
                int idx = i * 256 + tid;
                int row = idx >> 4;
                int k0  = (idx & 15) * 4;
                rb[i] = *(const float4*)(Bp + (long)(n0 + row) * ldb + kt * KT + k0);
            }
        } else {
            const float* Bb = Bp + (long)kt * KT * ldb + n0;
#pragma unroll
            for (int i = 0; i < 8; i++) {
                int idx = i * 256 + tid;
                int n  = idx & 127;
                int k0 = (idx >> 7) * 4;
                rb[i] = make_float4(Bb[(long)(k0 + 0) * ldb + n],
                                    Bb[(long)(k0 + 1) * ldb + n],
                                    Bb[(long)(k0 + 2) * ldb + n],
                                    Bb[(long)(k0 + 3) * ldb + n]);
            }
        }
    };
    // ---- stores: regs -> smem (split hi/lo, swizzled) ----
    auto storeA = [&](int buf) {
        char* ah = AH + buf * TB;
        char* al = AL + buf * TB;
#pragma unroll
        for (int i = 0; i < 8; i++) {
            int idx = i * 256 + tid;
            int row = idx >> 4;
            int k0  = (idx & 15) * 4;
            unsigned o = swz(row * 128 + k0 * 2);
            split_store(ra[i].x, ra[i].y, ra[i].z, ra[i].w, ah + o, al + o);
        }
    };
    auto storeB = [&](int buf) {
        char* bh = BH + buf * TB;
        char* bl = BL + buf * TB;
#pragma unroll
        for (int i = 0; i < 8; i++) {
            int idx = i * 256 + tid;
            int row, k0;
            if (TRANSB) { row = idx >> 4; k0 = (idx & 15) * 4; }
            else        { row = idx & 127; k0 = (idx >> 7) * 4; }
            unsigned o = swz(row * 128 + k0 * 2);
            split_store(rb[i].x, rb[i].y, rb[i].z, rb[i].w, bh + o, bl + o);
        }
    };

    const int nkt = K / KT;

    loadA(0); loadB(0);
    storeA(0); storeB(0);
    __syncthreads();

    const int arow = lane & 15, ach = lane >> 4;
    const int brow = lane & 7,  bch = (lane >> 3) & 1;

    for (int kt = 0; kt < nkt; kt++) {
        const int buf = kt & 1;
        if (kt + 1 < nkt) { loadA(kt + 1); loadB(kt + 1); }

        const unsigned ahb = uAH + buf * TB, alb = uAL + buf * TB;
        const unsigned bhb = uBH + buf * TB, blb = uBL + buf * TB;
#pragma unroll
        for (int ks = 0; ks < 4; ks++) {
            unsigned ah[4][4], al[4][4], bh[4][2], bl[4][2];
#pragma unroll
            for (int mt = 0; mt < 4; mt++) {
                unsigned o = swz((mw + mt * 16 + arow) * 128 + ks * 32 + 16 * ach);
                LDSM4(ah[mt], ahb + o);
                LDSM4(al[mt], alb + o);
            }
#pragma unroll
            for (int nt = 0; nt < 4; nt++) {
                unsigned o = swz((nw + nt * 8 + brow) * 128 + ks * 32 + 16 * bch);
                LDSM2(bh[nt], bhb + o);
                LDSM2(bl[nt], blb + o);
            }
#pragma unroll
            for (int mt = 0; mt < 4; mt++)
#pragma unroll
                for (int nt = 0; nt < 4; nt++) {
                    MMA(acc[mt][nt], ah[mt], bh[nt]);
                    MMA(acc[mt][nt], ah[mt], bl[nt]);
                    MMA(acc[mt][nt], al[mt], bh[nt]);
                }
        }
        __syncthreads();
        if (kt + 1 < nkt) {
            storeA(buf ^ 1); storeB(buf ^ 1);
            __syncthreads();
        }
    }

    // ---- epilogue ----
#pragma unroll
    for (int mt = 0; mt < 4; mt++) {
        int r0 = m0 + mw + mt * 16 + (lane >> 2);
#pragma unroll
        for (int nt = 0; nt < 4; nt++) {
            int c = n0 + nw + nt * 8 + (lane & 3) * 2;
            float b0 = BIAS ? bias[c] : 0.f;
            float b1 = BIAS ? bias[c + 1] : 0.f;
            float2 o0, o1;
            o0.x = alpha * acc[mt][nt][0] + b0;
            o0.y = alpha * acc[mt][nt][1] + b1;
            o1.x = alpha * acc[mt][nt][2] + b0;
            o1.y = alpha * acc[mt][nt][3] + b1;
            if (RELU) {
                o0.x = fmaxf(o0.x, 0.f); o0.y = fmaxf(o0.y, 0.f);
                o1.x = fmaxf(o1.x, 0.f); o1.y = fmaxf(o1.y, 0.f);
            }
            *(float2*)(C + (long)r0 * ldc + c)       = o0;
            *(float2*)(C + (long)(r0 + 8) * ldc + c) = o1;
        }
    }
}

// ---------------- small kernels ----------------------------------------------
__global__ void prep_kernel(const float* __restrict__ xin,
                            const float* __restrict__ bvec) {
    int idx = blockIdx.x * blockDim.x + threadIdx.x;
    if (idx >= MM * (DIMIN / 4)) return;
    int c4 = idx % (DIMIN / 4);
    float4 xv = ((const float4*)xin)[idx];
    float4 bv = ((const float4*)bvec)[c4];
    ((float4*)g_x)[idx] = make_float4(xv.x - bv.x, xv.y - bv.y, xv.z - bv.z, xv.w - bv.w);
}

__global__ void attn_scores_kernel() {
    int bh = blockIdx.x;
    int b = bh / NHEADS, h = bh % NHEADS;
    int t = blockIdx.y * 128 + threadIdx.x;

    __shared__ float kk[TT][DH_QK];
    const float* kbase = g_k + (long)b * TT * NEMBDS + h * DH_QK;
    for (int i = threadIdx.x; i < TT * (DH_QK / 4); i += 128) {
        int row = i >> 2, c4 = i & 3;
        ((float4*)&kk[row][0])[c4] =
            *(const float4*)(kbase + (long)row * NEMBDS + c4 * 4);
    }
    __syncthreads();

    float qv[DH_QK];
    const float* qb = g_q + (long)(b * TT + t) * NEMBDS + h * DH_QK;
#pragma unroll
    for (int d = 0; d < DH_QK; d++) qv[d] = qb[d];

    float* prow = g_probs + ((long)bh * TT + t) * TT;
    float mx = -1e30f;
    for (int tp = 0; tp <= t; tp++) {
        float s = 0.f;
#pragma unroll
        for (int d = 0; d < DH_QK; d++) s += qv[d] * kk[tp][d];
        s *= 0.25f;
        mx = fmaxf(mx, s);
        prow[tp] = s;
    }
    float sum = 0.f;
    for (int tp = 0; tp <= t; tp++) sum += __expf(prow[tp] - mx);
    float inv = 1.f / sum;
    for (int tp = 0; tp < TT; tp++) {
        float p = (tp <= t) ? __expf(prow[tp] - mx) * inv : 0.f;
        prow[tp] = p;
    }
}

__global__ void proj_kernel() {
    int m = blockIdx.x;
    int tid = threadIdx.x;
    const float* dz = g_Dz + (long)m * DIMIN;
    const float* x  = g_x  + (long)m * DIMIN;

    float num = 0.f, den = 0.f;
    for (int j = tid; j < DIMIN; j += 256) {
        float a = dz[j], c = x[j];
        num += a * c;
        den += a * a;
    }
#pragma unroll
    for (int o = 16; o > 0; o >>= 1) {
        num += __shfl_down_sync(0xFFFFFFFFu, num, o);
        den += __shfl_down_sync(0xFFFFFFFFu, den, o);
    }
    __shared__ float sn[8], sd[8];
    __shared__ float s_proj;
    int lane = tid & 31, wd = tid >> 5;
    if (lane == 0) { sn[wd] = num; sd[wd] = den; }
    __syncthreads();
    if (tid == 0) {
        float N = 0.f, Dd = 0.f;
#pragma unroll
        for (int i = 0; i < 8; i++) { N += sn[i]; Dd += sd[i]; }
        float p = N / (Dd + EPSV);
        s_proj = p;
        g_proj[m] = p;
    }
    __syncthreads();
    float p = s_proj;
    for (int j = tid; j < DIMIN; j += 256)
        g_x2[(long)m * DIMIN + j] = x[j] - p * dz[j];
}

__global__ void topk_zsum_kernel(const int* __restrict__ kvalp) {
    int m = blockIdx.x;
    int tid = threadIdx.x;

    __shared__ unsigned sv[WIDTH];
    __shared__ int hist[256];
    __shared__ int s_target;
    __shared__ unsigned s_prefix, s_mask;

    const float* zn = g_znov + (long)m * WIDTH;
    for (int j = tid; j < WIDTH; j += 256)
        sv[j] = __float_as_uint(zn[j]);
    if (tid == 0) { s_target = *kvalp; s_prefix = 0u; s_mask = 0u; }
    __syncthreads();

    for (int byte = 3; byte >= 0; --byte) {
        hist[tid] = 0;
        __syncthreads();
        int shift = byte * 8;
        unsigned pm = s_mask, pf = s_prefix;
        for (int j = tid; j < WIDTH; j += 256) {
            unsigned v = sv[j];
            if ((v & pm) == pf) atomicAdd(&hist[(v >> shift) & 255], 1);
        }
        __syncthreads();
        if (tid == 0) {
            int cum = 0, tgt = s_target, sel = 0;
            for (int bin = 255; bin >= 0; --bin) {
                int c = hist[bin];
                if (cum + c >= tgt) { sel = bin; break; }
                cum += c;
            }
            s_target = tgt - cum;
            s_prefix = pf | ((unsigned)sel << shift);
            s_mask   = pm | (0xFFu << shift);
        }
        __syncthreads();
    }
    unsigned tau = s_prefix;
    float p = g_proj[m];
    const float* zp = g_zpred + (long)m * WIDTH;
    float* out = g_zsum + (long)m * WIDTH;
    for (int j = tid; j < WIDTH; j += 256) {
        unsigned v = sv[j];
        float zval = (v >= tau) ? __uint_as_float(v) : 0.f;
        out[j] = zval + p * zp[j];
    }
}

// ---------------- launcher ---------------------------------------------------
#define SMEMSZ (8 * 128 * KT * 2)   /* 131072 bytes */

extern "C" void kernel_launch(void* const* d_in, const int* in_sizes, int n_in,
                              void* d_out, int out_size)
{
    const float* x_input = (const float*)d_in[0];
    const float* D       = (const float*)d_in[1];
    const float* bvec    = (const float*)d_in[2];
    const float* Wk      = (const float*)d_in[3];
    const float* bk      = (const float*)d_in[4];
    const float* Wq      = (const float*)d_in[5];
    const float* bq      = (const float*)d_in[6];
    const float* Wv      = (const float*)d_in[7];
    const float* bv      = (const float*)d_in[8];
    const float* Wo      = (const float*)d_in[9];
    const float* bo      = (const float*)d_in[10];
    const int*   kval    = (const int*)d_in[11];

    float *px, *px2, *pzin, *pq, *pk, *pv, *pprobs, *pattno,
          *pzpred, *pDz, *pzsum, *pznov;
    cudaGetSymbolAddress((void**)&px,     g_x);
    cudaGetSymbolAddress((void**)&px2,    g_x2);
    cudaGetSymbolAddress((void**)&pzin,   g_zin);
    cudaGetSymbolAddress((void**)&pq,     g_q);
    cudaGetSymbolAddress((void**)&pk,     g_k);
    cudaGetSymbolAddress((void**)&pv,     g_v);
    cudaGetSymbolAddress((void**)&pprobs, g_probs);
    cudaGetSymbolAddress((void**)&pattno, g_attno);
    cudaGetSymbolAddress((void**)&pzpred, g_zpred);
    cudaGetSymbolAddress((void**)&pDz,    g_Dz);
    cudaGetSymbolAddress((void**)&pznov,  g_znov);
    cudaGetSymbolAddress((void**)&pzsum,  g_zsum);

    cudaFuncSetAttribute(tgemm<true,  true,  false, false>, cudaFuncAttributeMaxDynamicSharedMemorySize, SMEMSZ);
    cudaFuncSetAttribute(tgemm<true,  false, true,  true >, cudaFuncAttributeMaxDynamicSharedMemorySize, SMEMSZ);
    cudaFuncSetAttribute(tgemm<true,  false, true,  false>, cudaFuncAttributeMaxDynamicSharedMemorySize, SMEMSZ);
    cudaFuncSetAttribute(tgemm<false, false, false, false>, cudaFuncAttributeMaxDynamicSharedMemorySize, SMEMSZ);
    cudaFuncSetAttribute(tgemm<true,  true,  true,  false>, cudaFuncAttributeMaxDynamicSharedMemorySize, SMEMSZ);
    cudaFuncSetAttribute(tgemm<false, false, true,  false>, cudaFuncAttributeMaxDynamicSharedMemorySize, SMEMSZ);

    // 1) x = x_input - b
    prep_kernel<<<(MM * (DIMIN / 4) + 255) / 256, 256>>>(x_input, bvec);

    // 2) z_in = relu(lam * x @ D^T)
    tgemm<true, true, false, false><<<dim3(WIDTH / 128, MM / 128, 1), 256, SMEMSZ>>>(
        px, DIMIN, D, DIMIN, pzin, WIDTH, DIMIN, LAM, nullptr, 0, 1, 0, 0, 0, 0);

    // 3) k = shift(z_in) @ Wk^T + bk
    tgemm<true, false, true, true><<<dim3(1, MM / 128, 1), 256, SMEMSZ>>>(
        pzin, WIDTH, Wk, WIDTH, pk, NEMBDS, WIDTH, 1.f, bk, 0, 1, 0, 0, 0, 0);

    // 4) q = z_in @ Wq^T + bq
    tgemm<true, false, true, false><<<dim3(1, MM / 128, 1), 256, SMEMSZ>>>(
        pzin, WIDTH, Wq, WIDTH, pq, NEMBDS, WIDTH, 1.f, bq, 0, 1, 0, 0, 0, 0);

    // 5) v = shift(z_in) @ Wv^T + bv
    tgemm<true, false, true, true><<<dim3(WIDTH / 128, MM / 128, 1), 256, SMEMSZ>>>(
        pzin, WIDTH, Wv, WIDTH, pv, WIDTH, WIDTH, 1.f, bv, 0, 1, 0, 0, 0, 0);

    // 6) causal softmax probs
    attn_scores_kernel<<<dim3(BB * NHEADS, TT / 128), 128>>>();

    // 7) o = P @ V  per (b,h)
    tgemm<false, false, false, false><<<dim3(DH_V / 128, TT / 128, BB * NHEADS), 256, SMEMSZ>>>(
        pprobs, TT, pv, WIDTH, pattno, WIDTH, TT, 1.f, nullptr,
        (long)TT * TT, NHEADS,
        (long)TT * WIDTH, (long)DH_V,
        (long)TT * WIDTH, (long)DH_V);

    // 8) z_pred_ = relu(o @ Wo^T + bo)
    tgemm<true, true, true, false><<<dim3(WIDTH / 128, MM / 128, 1), 256, SMEMSZ>>>(
        pattno, WIDTH, Wo, WIDTH, pzpred, WIDTH, WIDTH, 1.f, bo, 0, 1, 0, 0, 0, 0);

    // 9) Dz = z_pred_ @ D
    tgemm<false, false, false, false><<<dim3(DIMIN / 128, MM / 128, 1), 256, SMEMSZ>>>(
        pzpred, WIDTH, D, DIMIN, pDz, DIMIN, WIDTH, 1.f, nullptr, 0, 1, 0, 0, 0, 0);

    // 10) proj + residual
    proj_kernel<<<MM, 256>>>();

    // 11) z_novel = relu(lam * x2 @ D^T)
    tgemm<true, true, false, false><<<dim3(WIDTH / 128, MM / 128, 1), 256, SMEMSZ>>>(
        px2, DIMIN, D, DIMIN, pznov, WIDTH, DIMIN, LAM, nullptr, 0, 1, 0, 0, 0, 0);

    // 12) top-k + z sum
    topk_zsum_kernel<<<MM, 256>>>(kval);

    // 13) x_recons = zsum @ D + b
    tgemm<false, false, true, false><<<dim3(DIMIN / 128, MM / 128, 1), 256, SMEMSZ>>>(
        pzsum, WIDTH, D, DIMIN, (float*)d_out, DIMIN, WIDTH, 1.f, bvec, 0, 1, 0, 0, 0, 0);
}

// round 5
// speedup vs baseline: 5.4207x; 1.1937x over previous
#include <cuda_runtime.h>
#include <cuda_bf16.h>
#include <math.h>

#define BB      8
#define TT      512
#define DIMIN   768
#define WIDTH   8192
#define NHEADS  8
#define NEMBDS  128
#define DH_QK   16
#define DH_V    1024
#define MM      (BB * TT)          /* 4096 */
#define LAM     (1.0f / 3072.0f)
#define EPSV    1e-6f
#define KT      64                 /* K-tile elems (128B bf16 rows) */
#define NSTAGE  3
#define STB     65536              /* bytes per stage: Ah16K Al16K Bh16K Bl16K */

// ---------------- fp32 scratch ----------------------------------------------
__device__ float g_x     [MM * DIMIN];
__device__ float g_q     [MM * NEMBDS];
__device__ float g_k     [MM * NEMBDS];
__device__ float g_scores[(long)BB * NHEADS * TT * TT];
__device__ float g_Dz    [MM * DIMIN];
__device__ float g_zpred [MM * WIDTH];
__device__ float g_znov  [MM * WIDTH];
__device__ float g_proj  [MM];
__device__ float g_part  [2 * MM * DIMIN];           /* >= 8*MM*NEMBDS */

// ---------------- bf16 hi/lo split buffers ([0]=hi, [1]=lo) ------------------
__device__ __align__(256) __nv_bfloat16 s_x    [2][MM * DIMIN];
__device__ __align__(256) __nv_bfloat16 s_x2   [2][MM * DIMIN];
__device__ __align__(256) __nv_bfloat16 s_D    [2][WIDTH * DIMIN];
__device__ __align__(256) __nv_bfloat16 s_DT   [2][DIMIN * WIDTH];
__device__ __align__(256) __nv_bfloat16 s_Wk   [2][NEMBDS * WIDTH];
__device__ __align__(256) __nv_bfloat16 s_Wq   [2][NEMBDS * WIDTH];
__device__ __align__(256) __nv_bfloat16 s_Wv   [2][WIDTH * WIDTH];
__device__ __align__(256) __nv_bfloat16 s_Wo   [2][WIDTH * WIDTH];
__device__ __align__(256) __nv_bfloat16 s_zin  [2][MM * WIDTH];
__device__ __align__(256) __nv_bfloat16 s_v    [2][MM * WIDTH];
__device__ __align__(256) __nv_bfloat16 s_vT   [2][MM * WIDTH];
__device__ __align__(256) __nv_bfloat16 s_pr   [2][(long)BB * NHEADS * TT * TT];
__device__ __align__(256) __nv_bfloat16 s_at   [2][MM * WIDTH];
__device__ __align__(256) __nv_bfloat16 s_zp   [2][MM * WIDTH];
__device__ __align__(256) __nv_bfloat16 s_zs   [2][MM * WIDTH];

// ---------------- helpers ----------------------------------------------------
__device__ __forceinline__ unsigned smem_u32(const void* p) {
    unsigned a;
    asm("{ .reg .u64 t; cvta.to.shared.u64 t, %1; cvt.u32.u64 %0, t; }"
        : "=r"(a) : "l"(p));
    return a;
}
__device__ __forceinline__ unsigned swz(unsigned off) {
    return off ^ ((off >> 3) & 0x70);
}
__device__ __forceinline__ void cpa(unsigned dst, const void* src, int sz) {
    asm volatile("cp.async.cg.shared.global [%0], [%1], 16, %2;"
                 :: "r"(dst), "l"(src), "r"(sz) : "memory");
}
#define CPA_COMMIT() asm volatile("cp.async.commit_group;" ::: "memory")
#define CPA_WAIT1()  asm volatile("cp.async.wait_group 1;" ::: "memory")
#define CPA_WAIT0()  asm volatile("cp.async.wait_group 0;" ::: "memory")

#define LDSM4(r, a)                                                             \
    asm volatile("ldmatrix.sync.aligned.m8n8.x4.shared.b16 {%0,%1,%2,%3},[%4];" \
                 : "=r"((r)[0]), "=r"((r)[1]), "=r"((r)[2]), "=r"((r)[3])       \
                 : "r"(a))
#define LDSM2(r, a)                                                             \
    asm volatile("ldmatrix.sync.aligned.m8n8.x2.shared.b16 {%0,%1},[%2];"       \
                 : "=r"((r)[0]), "=r"((r)[1]) : "r"(a))
#define MMA(d, a, b)                                                            \
    asm volatile("mma.sync.aligned.m16n8k16.row.col.f32.bf16.bf16.f32 "         \
                 "{%0,%1,%2,%3},{%4,%5,%6,%7},{%8,%9},{%0,%1,%2,%3};"           \
                 : "+f"((d)[0]), "+f"((d)[1]), "+f"((d)[2]), "+f"((d)[3])       \
                 : "r"((a)[0]), "r"((a)[1]), "r"((a)[2]), "r"((a)[3]),          \
                   "r"((b)[0]), "r"((b)[1]))

__device__ __forceinline__ void split1(float v, __nv_bfloat16& h, __nv_bfloat16& l) {
    h = __float2bfloat16(v);
    l = __float2bfloat16(v - __bfloat162float(h));
}

// ---------------- GEMM: pre-split bf16 operands, cp.async 3-stage ------------
// C = act(alpha * A @ B^T + bias), A (M x K) hi/lo, B (N x K) hi/lo, row-major.
// EPI: 0 = fp32 (Cf), 1 = split (Ch/Cl), 2 = both.
// z: A += z*sA, B += z*sB, C offset = (z/zdiv)*sCo + (z%zdiv)*sCi.
template<bool RELU, bool BIAS, bool SHIFT, int EPI>
__global__ void __launch_bounds__(256, 1) tgemm(
    const __nv_bfloat16* __restrict__ Ah, const __nv_bfloat16* __restrict__ Al, int lda,
    const __nv_bfloat16* __restrict__ Bh, const __nv_bfloat16* __restrict__ Bl, int ldb,
    float* __restrict__ Cf, __nv_bfloat16* __restrict__ Ch, __nv_bfloat16* __restrict__ Cl,
    int ldc, int K, float alpha, const float* __restrict__ bias,
    long sA, long sB, int zdiv, long sCo, long sCi)
{
    extern __shared__ char sm[];
    const unsigned sb = smem_u32(sm);
    const int tid = threadIdx.x, wid = tid >> 5, lane = tid & 31;

    const int z = blockIdx.z;
    Ah += (long)z * sA;  Al += (long)z * sA;
    Bh += (long)z * sB;  Bl += (long)z * sB;
    const long coff = (long)(z / zdiv) * sCo + (long)(z % zdiv) * sCi;

    const int m0 = blockIdx.y * 128;
    const int n0 = blockIdx.x * 128;
    const int mw = (wid & 1) * 64;
    const int nw = (wid >> 1) * 32;

    float acc[4][4][4];
#pragma unroll
    for (int i = 0; i < 4; i++)
#pragma unroll
        for (int j = 0; j < 4; j++)
#pragma unroll
            for (int l = 0; l < 4; l++) acc[i][j][l] = 0.f;

    const int nkt = K / KT;

    // full tile coverage: 128 rows x 8 x 16B chunks = 1024 chunks per tensor
    auto issue = [&](int kt) {
        const unsigned st = sb + (kt % NSTAGE) * STB;
#pragma unroll
        for (int i = 0; i < 4; i++) {
            int idx = i * 256 + tid;            // 0..1023
            int row = idx >> 3, c = idx & 7;
            unsigned d = st + swz(row * 128 + c * 16);
            long off; int sz = 16;
            if (SHIFT) {
                int gr = m0 + row;
                int ok = (gr & (TT - 1)) != 0;
                off = (long)(ok ? gr - 1 : 0) * lda + kt * KT + c * 8;
                sz = ok ? 16 : 0;
            } else {
                off = (long)(m0 + row) * lda + kt * KT + c * 8;
            }
            cpa(d,         Ah + off, sz);
            cpa(d + 16384, Al + off, sz);
        }
#pragma unroll
        for (int i = 0; i < 4; i++) {
            int idx = i * 256 + tid;
            int row = idx >> 3, c = idx & 7;
            unsigned d = st + 32768 + swz(row * 128 + c * 16);
            long off = (long)(n0 + row) * ldb + kt * KT + c * 8;
            cpa(d,         Bh + off, 16);
            cpa(d + 16384, Bl + off, 16);
        }
        CPA_COMMIT();
    };

    issue(0);
    issue(1);

    const int arow = lane & 15, ach = lane >> 4;
    const int brow = lane & 7,  bch = (lane >> 3) & 1;

    for (int kt = 0; kt < nkt; kt++) {
        if (kt == nkt - 1) { CPA_WAIT0(); } else { CPA_WAIT1(); }
        __syncthreads();

        const unsigned st  = sb + (kt % NSTAGE) * STB;
        const unsigned ahb = st, alb = st + 16384, bhb = st + 32768, blb = st + 49152;
#pragma unroll
        for (int ks = 0; ks < 4; ks++) {
            unsigned ah[4][4], al[4][4];
#pragma unroll
            for (int mt = 0; mt < 4; mt++) {
                unsigned o = swz((mw + mt * 16 + arow) * 128 + ks * 32 + 16 * ach);
                LDSM4(ah[mt], ahb + o);
                LDSM4(al[mt], alb + o);
            }
#pragma unroll
            for (int nt = 0; nt < 4; nt++) {
                unsigned o = swz((nw + nt * 8 + brow) * 128 + ks * 32 + 16 * bch);
                unsigned bh[2], bl[2];
                LDSM2(bh, bhb + o);
                LDSM2(bl, blb + o);
#pragma unroll
                for (int mt = 0; mt < 4; mt++) {
                    MMA(acc[mt][nt], ah[mt], bh);
                    MMA(acc[mt][nt], ah[mt], bl);
                    MMA(acc[mt][nt], al[mt], bh);
                }
            }
        }
        __syncthreads();
        if (kt + 2 < nkt) issue(kt + 2);
    }

    // ---- epilogue ----
#pragma unroll
    for (int mt = 0; mt < 4; mt++) {
        int r0 = m0 + mw + mt * 16 + (lane >> 2);
#pragma unroll
        for (int nt = 0; nt < 4; nt++) {
            int c = n0 + nw + nt * 8 + (lane & 3) * 2;
            float b0 = BIAS ? bias[c] : 0.f;
            float b1 = BIAS ? bias[c + 1] : 0.f;
#pragma unroll
            for (int half = 0; half < 2; half++) {
                int r = r0 + half * 8;
                float v0 = alpha * acc[mt][nt][half * 2 + 0] + b0;
                float v1 = alpha * acc[mt][nt][half * 2 + 1] + b1;
                if (RELU) { v0 = fmaxf(v0, 0.f); v1 = fmaxf(v1, 0.f); }
                long e = coff + (long)r * ldc + c;
                if (EPI == 0 || EPI == 2)
                    *(float2*)(Cf + e) = make_float2(v0, v1);
                if (EPI == 1 || EPI == 2) {
                    __nv_bfloat162 h = __floats2bfloat162_rn(v0, v1);
                    float r0f = v0 - __bfloat162float(h.x);
                    float r1f = v1 - __bfloat162float(h.y);
                    __nv_bfloat162 l = __floats2bfloat162_rn(r0f, r1f);
                    *(__nv_bfloat162*)(Ch + e) = h;
                    *(__nv_bfloat162*)(Cl + e) = l;
                }
            }
        }
    }
}

// ---------------- split / transpose kernels ----------------------------------
__global__ void wsplit_kernel(const float* __restrict__ in,
                              __nv_bfloat16* __restrict__ hi,
                              __nv_bfloat16* __restrict__ lo, long n4) {
    long i = (long)blockIdx.x * blockDim.x + threadIdx.x;
    if (i >= n4) return;
    float4 v = ((const float4*)in)[i];
    __nv_bfloat162 h01 = __floats2bfloat162_rn(v.x, v.y);
    __nv_bfloat162 h23 = __floats2bfloat162_rn(v.z, v.w);
    __nv_bfloat162 l01 = __floats2bfloat162_rn(v.x - __bfloat162float(h01.x),
                                               v.y - __bfloat162float(h01.y));
    __nv_bfloat162 l23 = __floats2bfloat162_rn(v.z - __bfloat162float(h23.x),
                                               v.w - __bfloat162float(h23.y));
    ((uint2*)hi)[i] = make_uint2(*(unsigned*)&h01, *(unsigned*)&h23);
    ((uint2*)lo)[i] = make_uint2(*(unsigned*)&l01, *(unsigned*)&l23);
}

__global__ void prep_kernel(const float* __restrict__ xin,
                            const float* __restrict__ bvec) {
    long i = (long)blockIdx.x * blockDim.x + threadIdx.x;
    if (i >= MM * (DIMIN / 4)) return;
    int c4 = (int)(i % (DIMIN / 4));
    float4 xv = ((const float4*)xin)[i];
    float4 bv = ((const float4*)bvec)[c4];
    float4 r = make_float4(xv.x - bv.x, xv.y - bv.y, xv.z - bv.z, xv.w - bv.w);
    ((float4*)g_x)[i] = r;
    __nv_bfloat162 h01 = __floats2bfloat162_rn(r.x, r.y);
    __nv_bfloat162 h23 = __floats2bfloat162_rn(r.z, r.w);
    __nv_bfloat162 l01 = __floats2bfloat162_rn(r.x - __bfloat162float(h01.x),
                                               r.y - __bfloat162float(h01.y));
    __nv_bfloat162 l23 = __floats2bfloat162_rn(r.z - __bfloat162float(h23.x),
                                               r.w - __bfloat162float(h23.y));
    ((uint2*)&s_x[0][0])[i] = make_uint2(*(unsigned*)&h01, *(unsigned*)&h23);
    ((uint2*)&s_x[1][0])[i] = make_uint2(*(unsigned*)&l01, *(unsigned*)&l23);
}

// DT[n][k] = D[k][n], split  (D: WIDTH x DIMIN)
__global__ void dtsplit_kernel(const float* __restrict__ D) {
    __shared__ float tl[32][33];
    int n0 = blockIdx.x * 32, k0 = blockIdx.y * 32;
    int tx = threadIdx.x, ty = threadIdx.y;     // (32, 8)
#pragma unroll
    for (int j = 0; j < 4; j++)
        tl[ty + j * 8][tx] = D[(long)(k0 + ty + j * 8) * DIMIN + n0 + tx];
    __syncthreads();
#pragma unroll
    for (int j = 0; j < 4; j++) {
        int nr = ty + j * 8;
        float v = tl[tx][nr];
        __nv_bfloat16 h, l; split1(v, h, l);
        long o = (long)(n0 + nr) * WIDTH + k0 + tx;
        s_DT[0][o] = h; s_DT[1][o] = l;
    }
}

// vT[(b*8+h)*1024+d][t] = v[b*512+t][h*1024+d]   (bf16 hi & lo)
__global__ void vtrans_kernel() {
    __shared__ __nv_bfloat16 tl[2][32][33];
    int b = blockIdx.z;
    int d0 = blockIdx.x * 32;
    int t0 = blockIdx.y * 32;
    int tx = threadIdx.x, ty = threadIdx.y;   // (32, 8)
#pragma unroll
    for (int j = 0; j < 4; j++) {
        int r = ty + j * 8;
        long src = (long)(b * TT + t0 + r) * WIDTH + d0 + tx;
        tl[0][r][tx] = s_v[0][src];
        tl[1][r][tx] = s_v[1][src];
    }
    __syncthreads();
    int h = d0 >> 10, dbase = d0 & 1023;
#pragma unroll
    for (int j = 0; j < 4; j++) {
        int dr = ty + j * 8;
        long orow = (long)(b * NHEADS + h) * DH_V + dbase + dr;
        long dst = orow * TT + t0 + tx;
        s_vT[0][dst] = tl[0][tx][dr];
        s_vT[1][dst] = tl[1][tx][dr];
    }
}

// ---------------- split-K reduce ---------------------------------------------
template<bool BIAS>
__global__ void reduce_kernel(const float* __restrict__ part, long slab, int S,
                              float* __restrict__ out, const float* __restrict__ bias,
                              int N, long n4) {
    long i = (long)blockIdx.x * blockDim.x + threadIdx.x;
    if (i >= n4) return;
    float4 s = ((const float4*)part)[i];
    for (int k = 1; k < S; k++) {
        float4 p = ((const float4*)(part + (long)k * slab))[i];
        s.x += p.x; s.y += p.y; s.z += p.z; s.w += p.w;
    }
    if (BIAS) {
        int c = (int)((i * 4) % N);
        s.x += bias[c]; s.y += bias[c + 1]; s.z += bias[c + 2]; s.w += bias[c + 3];
    }
    ((float4*)out)[i] = s;
}

// ---------------- attention scores + softmax (writes split probs) ------------
__global__ void attn_scores_kernel() {
    int bh = blockIdx.x;
    int b = bh / NHEADS, h = bh % NHEADS;
    int t = blockIdx.y * 128 + threadIdx.x;

    __shared__ float kk[TT][DH_QK];
    const float* kbase = g_k + (long)b * TT * NEMBDS + h * DH_QK;
    for (int i = threadIdx.x; i < TT * (DH_QK / 4); i += 128) {
        int row = i >> 2, c4 = i & 3;
        ((float4*)&kk[row][0])[c4] =
            *(const float4*)(kbase + (long)row * NEMBDS + c4 * 4);
    }
    __syncthreads();

    float qv[DH_QK];
    const float* qb = g_q + (long)(b * TT + t) * NEMBDS + h * DH_QK;
#pragma unroll
    for (int d = 0; d < DH_QK; d++) qv[d] = qb[d];

    float* srow = g_scores + ((long)bh * TT + t) * TT;
    float mx = -1e30f;
    for (int tp = 0; tp <= t; tp++) {
        float s = 0.f;
#pragma unroll
        for (int d = 0; d < DH_QK; d++) s += qv[d] * kk[tp][d];
        s *= 0.25f;
        mx = fmaxf(mx, s);
        srow[tp] = s;
    }
    float sum = 0.f;
    for (int tp = 0; tp <= t; tp++) sum += __expf(srow[tp] - mx);
    float inv = 1.f / sum;
    long base = ((long)bh * TT + t) * TT;
    for (int tp = 0; tp < TT; tp++) {
        float p = (tp <= t) ? __expf(srow[tp] - mx) * inv : 0.f;
        __nv_bfloat16 hh, ll; split1(p, hh, ll);
        s_pr[0][base + tp] = hh;
        s_pr[1][base + tp] = ll;
    }
}

// ---------------- projection + residual (writes split x2) --------------------
__global__ void proj_kernel() {
    int m = blockIdx.x;
    int tid = threadIdx.x;
    const float* dz = g_Dz + (long)m * DIMIN;
    const float* x  = g_x  + (long)m * DIMIN;

    float num = 0.f, den = 0.f;
    for (int j = tid; j < DIMIN; j += 256) {
        float a = dz[j], c = x[j];
        num += a * c;
        den += a * a;
    }
#pragma unroll
    for (int o = 16; o > 0; o >>= 1) {
        num += __shfl_down_sync(0xFFFFFFFFu, num, o);
        den += __shfl_down_sync(0xFFFFFFFFu, den, o);
    }
    __shared__ float sn[8], sd[8];
    __shared__ float s_projv;
    int lane = tid & 31, wd = tid >> 5;
    if (lane == 0) { sn[wd] = num; sd[wd] = den; }
    __syncthreads();
    if (tid == 0) {
        float N = 0.f, Dd = 0.f;
#pragma unroll
        for (int i = 0; i < 8; i++) { N += sn[i]; Dd += sd[i]; }
        float p = N / (Dd + EPSV);
        s_projv = p;
        g_proj[m] = p;
    }
    __syncthreads();
    float p = s_projv;
    for (int j = tid; j < DIMIN; j += 256) {
        float v = x[j] - p * dz[j];
        __nv_bfloat16 h, l; split1(v, h, l);
        long o = (long)m * DIMIN + j;
        s_x2[0][o] = h; s_x2[1][o] = l;
    }
}

// ---------------- top-k + z sum (writes split zsum) --------------------------
__global__ void topk_zsum_kernel(const int* __restrict__ kvalp) {
    int m = blockIdx.x;
    int tid = threadIdx.x;

    __shared__ unsigned sv[WIDTH];
    __shared__ int hist[256];
    __shared__ int s_target;
    __shared__ unsigned s_prefix, s_mask;

    const float* zn = g_znov + (long)m * WIDTH;
    for (int j = tid; j < WIDTH; j += 256)
        sv[j] = __float_as_uint(zn[j]);
    if (tid == 0) { s_target = *kvalp; s_prefix = 0u; s_mask = 0u; }
    __syncthreads();

    for (int byte = 3; byte >= 0; --byte) {
        hist[tid] = 0;
        __syncthreads();
        int shift = byte * 8;
        unsigned pm = s_mask, pf = s_prefix;
        for (int j = tid; j < WIDTH; j += 256) {
            unsigned v = sv[j];
            if ((v & pm) == pf) atomicAdd(&hist[(v >> shift) & 255], 1);
        }
        __syncthreads();
        if (tid == 0) {
            int cum = 0, tgt = s_target, sel = 0;
            for (int bin = 255; bin >= 0; --bin) {
                int c = hist[bin];
                if (cum + c >= tgt) { sel = bin; break; }
                cum += c;
            }
            s_target = tgt - cum;
            s_prefix = pf | ((unsigned)sel << shift);
            s_mask   = pm | (0xFFu << shift);
        }
        __syncthreads();
    }
    unsigned tau = s_prefix;
    float p = g_proj[m];
    const float* zp = g_zpred + (long)m * WIDTH;
    for (int j = tid; j < WIDTH; j += 256) {
        unsigned v = sv[j];
        float zval = (v >= tau) ? __uint_as_float(v) : 0.f;
        float o = zval + p * zp[j];
        __nv_bfloat16 h, l; split1(o, h, l);
        long e = (long)m * WIDTH + j;
        s_zs[0][e] = h; s_zs[1][e] = l;
    }
}

// ---------------- launcher ---------------------------------------------------
#define SMEMSZ (NSTAGE * STB)   /* 196608 */

extern "C" void kernel_launch(void* const* d_in, const int* in_sizes, int n_in,
                              void* d_out, int out_size)
{
    const float* x_input = (const float*)d_in[0];
    const float* D       = (const float*)d_in[1];
    const float* bvec    = (const float*)d_in[2];
    const float* Wk      = (const float*)d_in[3];
    const float* bk      = (const float*)d_in[4];
    const float* Wq      = (const float*)d_in[5];
    const float* bq      = (const float*)d_in[6];
    const float* Wv      = (const float*)d_in[7];
    const float* bv      = (const float*)d_in[8];
    const float* Wo      = (const float*)d_in[9];
    const float* bo      = (const float*)d_in[10];
    const int*   kval    = (const int*)d_in[11];

    float *pq, *pk, *pDz, *pzpred, *pznov, *ppart;
    cudaGetSymbolAddress((void**)&pq,     g_q);
    cudaGetSymbolAddress((void**)&pk,     g_k);
    cudaGetSymbolAddress((void**)&pDz,    g_Dz);
    cudaGetSymbolAddress((void**)&pzpred, g_zpred);
    cudaGetSymbolAddress((void**)&pznov,  g_znov);
    cudaGetSymbolAddress((void**)&ppart,  g_part);

    __nv_bfloat16 *pxs, *px2s, *pDs, *pDTs, *pWks, *pWqs, *pWvs, *pWos,
                  *pzins, *pvs, *pvTs, *pprs, *pats, *pzps, *pzss;
    cudaGetSymbolAddress((void**)&pxs,   s_x);
    cudaGetSymbolAddress((void**)&px2s,  s_x2);
    cudaGetSymbolAddress((void**)&pDs,   s_D);
    cudaGetSymbolAddress((void**)&pDTs,  s_DT);
    cudaGetSymbolAddress((void**)&pWks,  s_Wk);
    cudaGetSymbolAddress((void**)&pWqs,  s_Wq);
    cudaGetSymbolAddress((void**)&pWvs,  s_Wv);
    cudaGetSymbolAddress((void**)&pWos,  s_Wo);
    cudaGetSymbolAddress((void**)&pzins, s_zin);
    cudaGetSymbolAddress((void**)&pvs,   s_v);
    cudaGetSymbolAddress((void**)&pvTs,  s_vT);
    cudaGetSymbolAddress((void**)&pprs,  s_pr);
    cudaGetSymbolAddress((void**)&pats,  s_at);
    cudaGetSymbolAddress((void**)&pzps,  s_zp);
    cudaGetSymbolAddress((void**)&pzss,  s_zs);

    cudaFuncSetAttribute(tgemm<true,  false, false, 1>, cudaFuncAttributeMaxDynamicSharedMemorySize, SMEMSZ);
    cudaFuncSetAttribute(tgemm<false, false, true,  0>, cudaFuncAttributeMaxDynamicSharedMemorySize, SMEMSZ);
    cudaFuncSetAttribute(tgemm<false, false, false, 0>, cudaFuncAttributeMaxDynamicSharedMemorySize, SMEMSZ);
    cudaFuncSetAttribute(tgemm<false, true,  true,  1>, cudaFuncAttributeMaxDynamicSharedMemorySize, SMEMSZ);
    cudaFuncSetAttribute(tgemm<false, false, false, 1>, cudaFuncAttributeMaxDynamicSharedMemorySize, SMEMSZ);
    cudaFuncSetAttribute(tgemm<true,  true,  false, 2>, cudaFuncAttributeMaxDynamicSharedMemorySize, SMEMSZ);
    cudaFuncSetAttribute(tgemm<true,  false, false, 0>, cudaFuncAttributeMaxDynamicSharedMemorySize, SMEMSZ);

    // ---- input prep + weight splits ----
    prep_kernel<<<(MM * (DIMIN / 4) + 255) / 256, 256>>>(x_input, bvec);
    wsplit_kernel<<<((long)WIDTH * DIMIN / 4 + 255) / 256, 256>>>(D,  pDs,  pDs  + (long)WIDTH * DIMIN,  (long)WIDTH * DIMIN / 4);
    wsplit_kernel<<<((long)NEMBDS * WIDTH / 4 + 255) / 256, 256>>>(Wk, pWks, pWks + (long)NEMBDS * WIDTH, (long)NEMBDS * WIDTH / 4);
    wsplit_kernel<<<((long)NEMBDS * WIDTH / 4 + 255) / 256, 256>>>(Wq, pWqs, pWqs + (long)NEMBDS * WIDTH, (long)NEMBDS * WIDTH / 4);
    wsplit_kernel<<<((long)WIDTH * WIDTH / 4 + 255) / 256, 256>>>(Wv, pWvs, pWvs + (long)WIDTH * WIDTH, (long)WIDTH * WIDTH / 4);
    wsplit_kernel<<<((long)WIDTH * WIDTH / 4 + 255) / 256, 256>>>(Wo, pWos, pWos + (long)WIDTH * WIDTH, (long)WIDTH * WIDTH / 4);
    dtsplit_kernel<<<dim3(DIMIN / 32, WIDTH / 32), dim3(32, 8)>>>(D);

    const long NW = (long)MM * WIDTH;
    const long ND = (long)MM * DIMIN;
    const long NE = (long)NEMBDS * WIDTH;
    const long WW = (long)WIDTH * WIDTH;
    const long WD = (long)WIDTH * DIMIN;
    const long PP = (long)BB * NHEADS * TT * TT;

    // 2) z_in = relu(lam * x @ D^T)  -> split
    tgemm<true, false, false, 1><<<dim3(WIDTH / 128, MM / 128, 1), 256, SMEMSZ>>>(
        pxs, pxs + ND, DIMIN, pDs, pDs + WD, DIMIN,
        nullptr, pzins, pzins + NW, WIDTH, DIMIN, LAM, nullptr, 0, 0, 1, 0, 0);

    // 3) k partials (shifted A), split-K 8 -> reduce + bk
    tgemm<false, false, true, 0><<<dim3(1, MM / 128, 8), 256, SMEMSZ>>>(
        pzins, pzins + NW, WIDTH, pWks, pWks + NE, WIDTH,
        ppart, nullptr, nullptr, NEMBDS, WIDTH / 8, 1.f, nullptr,
        WIDTH / 8, WIDTH / 8, 1, (long)MM * NEMBDS, 0);
    reduce_kernel<true><<<((long)MM * NEMBDS / 4 + 255) / 256, 256>>>(
        ppart, (long)MM * NEMBDS, 8, pk, bk, NEMBDS, (long)MM * NEMBDS / 4);

    // 4) q partials, split-K 8 -> reduce + bq
    tgemm<false, false, false, 0><<<dim3(1, MM / 128, 8), 256, SMEMSZ>>>(
        pzins, pzins + NW, WIDTH, pWqs, pWqs + NE, WIDTH,
        ppart, nullptr, nullptr, NEMBDS, WIDTH / 8, 1.f, nullptr,
        WIDTH / 8, WIDTH / 8, 1, (long)MM * NEMBDS, 0);
    reduce_kernel<true><<<((long)MM * NEMBDS / 4 + 255) / 256, 256>>>(
        ppart, (long)MM * NEMBDS, 8, pq, bq, NEMBDS, (long)MM * NEMBDS / 4);

    // 5) v = shift(z_in) @ Wv^T + bv  -> split, then transpose
    tgemm<false, true, true, 1><<<dim3(WIDTH / 128, MM / 128, 1), 256, SMEMSZ>>>(
        pzins, pzins + NW, WIDTH, pWvs, pWvs + WW, WIDTH,
        nullptr, pvs, pvs + NW, WIDTH, WIDTH, 1.f, bv, 0, 0, 1, 0, 0);
    vtrans_kernel<<<dim3(WIDTH / 32, TT / 32, BB), dim3(32, 8)>>>();

    // 6) scores + softmax -> split probs
    attn_scores_kernel<<<dim3(BB * NHEADS, TT / 128), 128>>>();

    // 7) o = P @ V^T per (b,h) -> split attno
    tgemm<false, false, false, 1><<<dim3(DH_V / 128, TT / 128, BB * NHEADS), 256, SMEMSZ>>>(
        pprs, pprs + PP, TT, pvTs, pvTs + NW, TT,
        nullptr, pats, pats + NW, WIDTH, TT, 1.f, nullptr,
        (long)TT * TT, (long)DH_V * TT, NHEADS, (long)TT * WIDTH, (long)DH_V);

    // 8) z_pred_ = relu(o @ Wo^T + bo) -> fp32 + split
    tgemm<true, true, false, 2><<<dim3(WIDTH / 128, MM / 128, 1), 256, SMEMSZ>>>(
        pats, pats + NW, WIDTH, pWos, pWos + WW, WIDTH,
        pzpred, pzps, pzps + NW, WIDTH, WIDTH, 1.f, bo, 0, 0, 1, 0, 0);

    // 9) Dz = z_pred_ @ D  (via DT), split-K 2 -> reduce
    tgemm<false, false, false, 0><<<dim3(DIMIN / 128, MM / 128, 2), 256, SMEMSZ>>>(
        pzps, pzps + NW, WIDTH, pDTs, pDTs + WD, WIDTH,
        ppart, nullptr, nullptr, DIMIN, WIDTH / 2, 1.f, nullptr,
        WIDTH / 2, WIDTH / 2, 1, ND, 0);
    reduce_kernel<false><<<(ND / 4 + 255) / 256, 256>>>(
        ppart, ND, 2, pDz, nullptr, DIMIN, ND / 4);

    // 10) proj + residual -> split x2
    proj_kernel<<<MM, 256>>>();

    // 11) z_novel = relu(lam * x2 @ D^T) -> fp32
    tgemm<true, false, false, 0><<<dim3(WIDTH / 128, MM / 128, 1), 256, SMEMSZ>>>(
        px2s, px2s + ND, DIMIN, pDs, pDs + WD, DIMIN,
        pznov, nullptr, nullptr, WIDTH, DIMIN, LAM, nullptr, 0, 0, 1, 0, 0);

    // 12) top-k + z sum -> split zsum
    topk_zsum_kernel<<<MM, 256>>>(kval);

    // 13) x_recons = zsum @ D + b (via DT), split-K 2 -> reduce + bvec -> d_out
    tgemm<false, false, false, 0><<<dim3(DIMIN / 128, MM / 128, 2), 256, SMEMSZ>>>(
        pzss, pzss + NW, WIDTH, pDTs, pDTs + WD, WIDTH,
        ppart, nullptr, nullptr, DIMIN, WIDTH / 2, 1.f, nullptr,
        WIDTH / 2, WIDTH / 2, 1, ND, 0);
    reduce_kernel<true><<<(ND / 4 + 255) / 256, 256>>>(
        ppart, ND, 2, (float*)d_out, bvec, DIMIN, ND / 4);
}